// round 1
// baseline (speedup 1.0000x reference)
#include <cuda_runtime.h>
#include <math.h>

#define NB 64
#define NT 512
#define NVARS 16
#define VDIM 16
#define DD 64
#define NTOK (NB*NT)
#define TPB 256
#define LN_EPS 1e-3f

// scratch for context projection [B, N_VARS, D]
__device__ __align__(16) float g_cproj[NB * NVARS * DD];

// ---------------------------------------------------------------------------
// Kernel A: cproj[b][n][e] = sum_d context[b][d] * Wctx[n][d][e]
// ---------------------------------------------------------------------------
__global__ void cproj_kernel(const float* __restrict__ context,
                             const float* __restrict__ Wctx) {
    int bb = blockIdx.x, n = blockIdx.y, e = threadIdx.x;
    const float* ctx = context + bb * DD;
    const float* W = Wctx + (size_t)n * DD * DD;
    float acc = 0.f;
#pragma unroll 8
    for (int d = 0; d < DD; ++d)
        acc = fmaf(ctx[d], W[d * DD + e], acc);
    g_cproj[((size_t)bb * NVARS + n) * DD + e] = acc;
}

// ---------------------------------------------------------------------------
// Kernel C: selection weights = softmax(inputs @ Ws + bs) -> wout [NTOK][16]
// ---------------------------------------------------------------------------
__global__ __launch_bounds__(TPB) void weights_kernel(
    const float* __restrict__ inputs, const float* __restrict__ Ws,
    const float* __restrict__ bs, float* __restrict__ wout) {
    __shared__ __align__(16) float ws_s[256 * 16];
    __shared__ __align__(16) float bs_s[16];
    int tid = threadIdx.x;
    for (int i = tid; i < 256 * 16; i += TPB) ws_s[i] = Ws[i];
    if (tid < 16) bs_s[tid] = bs[tid];
    __syncthreads();

    int token = blockIdx.x * TPB + tid;
    const float4* xp = (const float4*)(inputs + (size_t)token * 256);
    float4 lg[4];
#pragma unroll
    for (int j = 0; j < 4; j++) lg[j] = ((const float4*)bs_s)[j];

#pragma unroll 4
    for (int f4 = 0; f4 < 64; ++f4) {
        float4 xv = xp[f4];
        const float* wr = ws_s + f4 * 64;
#pragma unroll
        for (int c = 0; c < 4; c++) {
            float x = (c == 0) ? xv.x : (c == 1) ? xv.y : (c == 2) ? xv.z : xv.w;
            const float4* w4 = (const float4*)(wr + c * 16);
#pragma unroll
            for (int j = 0; j < 4; j++) {
                float4 w = w4[j];
                lg[j].x = fmaf(x, w.x, lg[j].x);
                lg[j].y = fmaf(x, w.y, lg[j].y);
                lg[j].z = fmaf(x, w.z, lg[j].z);
                lg[j].w = fmaf(x, w.w, lg[j].w);
            }
        }
    }

    float l[16];
#pragma unroll
    for (int j = 0; j < 4; j++) {
        l[4 * j + 0] = lg[j].x; l[4 * j + 1] = lg[j].y;
        l[4 * j + 2] = lg[j].z; l[4 * j + 3] = lg[j].w;
    }
    float mx = l[0];
#pragma unroll
    for (int i = 1; i < 16; i++) mx = fmaxf(mx, l[i]);
    float s = 0.f;
#pragma unroll
    for (int i = 0; i < 16; i++) { l[i] = expf(l[i] - mx); s += l[i]; }
    float inv = 1.f / s;
    float4* op = (float4*)(wout + (size_t)token * 16);
#pragma unroll
    for (int j = 0; j < 4; j++) {
        float4 o;
        o.x = l[4 * j + 0] * inv; o.y = l[4 * j + 1] * inv;
        o.z = l[4 * j + 2] * inv; o.w = l[4 * j + 3] * inv;
        op[j] = o;
    }
}

// ---------------------------------------------------------------------------
// Main fused kernel helpers
// ---------------------------------------------------------------------------
__device__ __forceinline__ float eluf(float x) { return x > 0.f ? x : expm1f(x); }
__device__ __forceinline__ float sigm(float x) { return 1.f / (1.f + expf(-x)); }

// acc[d] += sum_k Scol[k]*W[k][d]; Scol strided by TPB (thread-private column)
__device__ __forceinline__ void matvec_acc(const float* __restrict__ W,
                                           const float* __restrict__ Scol,
                                           int K, float4 acc[16]) {
#pragma unroll 2
    for (int k = 0; k < K; ++k) {
        float a = Scol[k * TPB];
        const float4* wr = (const float4*)(W + k * DD);
#pragma unroll
        for (int i = 0; i < 16; ++i) {
            float4 w = wr[i];
            acc[i].x = fmaf(a, w.x, acc[i].x);
            acc[i].y = fmaf(a, w.y, acc[i].y);
            acc[i].z = fmaf(a, w.z, acc[i].z);
            acc[i].w = fmaf(a, w.w, acc[i].w);
        }
    }
}

__device__ __forceinline__ void store_vec(float* __restrict__ col, const float4 v[16]) {
#pragma unroll
    for (int i = 0; i < 16; i++) {
        col[(4 * i + 0) * TPB] = v[i].x;
        col[(4 * i + 1) * TPB] = v[i].y;
        col[(4 * i + 2) * TPB] = v[i].z;
        col[(4 * i + 3) * TPB] = v[i].w;
    }
}

__device__ __forceinline__ void load_b(const float* __restrict__ bsm, float4 v[16]) {
#pragma unroll
    for (int i = 0; i < 16; i++) v[i] = ((const float4*)bsm)[i];
}

// ---------------------------------------------------------------------------
// Main fused kernel: per-token chain over 16 vars, weighted selection
// smem: Wt(1024) | Wp,W1,W2,Wg(4*4096) | biases(8*64) | S(64*256) | R(64*256)
// ---------------------------------------------------------------------------
__global__ __launch_bounds__(TPB, 1) void vsn_main_kernel(
    const float* __restrict__ inputs,
    const float* __restrict__ Wt, const float* __restrict__ bt,
    const float* __restrict__ W1, const float* __restrict__ b1,
    const float* __restrict__ W2, const float* __restrict__ b2,
    const float* __restrict__ Wg, const float* __restrict__ bg,
    const float* __restrict__ Wp, const float* __restrict__ bp,
    const float* __restrict__ gamma_, const float* __restrict__ beta_,
    const float* __restrict__ wsel,
    float* __restrict__ selected) {
    extern __shared__ __align__(16) float smem[];
    float* Wt_s = smem;                 // 1024
    float* Wp_s = Wt_s + VDIM * DD;     // 4096 each
    float* W1_s = Wp_s + DD * DD;
    float* W2_s = W1_s + DD * DD;
    float* Wg_s = W2_s + DD * DD;
    float* bias_s = Wg_s + DD * DD;     // 8*64
    float* S = bias_s + 8 * DD;         // 64*TPB
    float* R = S + DD * TPB;            // 64*TPB

    const int tid = threadIdx.x;
    const int token = blockIdx.x * TPB + tid;
    const int b = token / NT;
    float* Scol = S + tid;
    float* Rcol = R + tid;

    float4 sel[16];
#pragma unroll
    for (int i = 0; i < 16; i++) sel[i] = make_float4(0.f, 0.f, 0.f, 0.f);

    for (int n = 0; n < NVARS; ++n) {
        __syncthreads();  // previous iter's smem reads done
        // cooperative weight loads (Wt_s..Wg_s contiguous region)
        {
            const float4* s0 = (const float4*)(Wt + (size_t)n * VDIM * DD);
            float4* d0 = (float4*)Wt_s;
            for (int i = tid; i < 256; i += TPB) d0[i] = s0[i];
            const float4* s1 = (const float4*)(Wp + (size_t)n * DD * DD);
            float4* d1 = (float4*)Wp_s;
            for (int i = tid; i < 1024; i += TPB) d1[i] = s1[i];
            const float4* s2 = (const float4*)(W1 + (size_t)n * DD * DD);
            float4* d2 = (float4*)W1_s;
            for (int i = tid; i < 1024; i += TPB) d2[i] = s2[i];
            const float4* s3 = (const float4*)(W2 + (size_t)n * DD * DD);
            float4* d3 = (float4*)W2_s;
            for (int i = tid; i < 1024; i += TPB) d3[i] = s3[i];
            const float4* s4 = (const float4*)(Wg + (size_t)n * DD * DD);
            float4* d4 = (float4*)Wg_s;
            for (int i = tid; i < 1024; i += TPB) d4[i] = s4[i];
        }
        if (tid < DD) {
            bias_s[0 * DD + tid] = bt[n * DD + tid];
            bias_s[1 * DD + tid] = bp[n * DD + tid];
            bias_s[2 * DD + tid] = b1[n * DD + tid];
            bias_s[3 * DD + tid] = b2[n * DD + tid];
            bias_s[4 * DD + tid] = bg[n * DD + tid];
            bias_s[5 * DD + tid] = gamma_[n * DD + tid];
            bias_s[6 * DD + tid] = beta_[n * DD + tid];
        }
        __syncthreads();

        // stage x slice [16] into S rows 0..15
        {
            const float4* xp = (const float4*)(inputs + (size_t)token * 256 + n * VDIM);
#pragma unroll
            for (int i = 0; i < 4; i++) {
                float4 xv = xp[i];
                Scol[(4 * i + 0) * TPB] = xv.x;
                Scol[(4 * i + 1) * TPB] = xv.y;
                Scol[(4 * i + 2) * TPB] = xv.z;
                Scol[(4 * i + 3) * TPB] = xv.w;
            }
        }

        float4 regA[16], regC[16];
        // t = x @ Wt + bt
        load_b(bias_s + 0 * DD, regA);
        matvec_acc(Wt_s, Scol, VDIM, regA);
        store_vec(Scol, regA);                 // S = t
        // residual = t @ Wp + bp
        load_b(bias_s + 1 * DD, regC);
        matvec_acc(Wp_s, Scol, DD, regC);
        store_vec(Rcol, regC);                 // R = residual
        // a = t + cproj
        {
            const float4* cp = (const float4*)(g_cproj + ((size_t)b * NVARS + n) * DD);
#pragma unroll
            for (int i = 0; i < 16; i++) {
                float4 c4 = cp[i];
                regA[i].x += c4.x; regA[i].y += c4.y;
                regA[i].z += c4.z; regA[i].w += c4.w;
            }
            store_vec(Scol, regA);             // S = a
        }
        // h1 = elu(a @ W1 + b1)
        load_b(bias_s + 2 * DD, regC);
        matvec_acc(W1_s, Scol, DD, regC);
#pragma unroll
        for (int i = 0; i < 16; i++) {
            regC[i].x = eluf(regC[i].x); regC[i].y = eluf(regC[i].y);
            regC[i].z = eluf(regC[i].z); regC[i].w = eluf(regC[i].w);
        }
        store_vec(Scol, regC);                 // S = h1
        // h2 = h1 @ W2 + b2
        load_b(bias_s + 3 * DD, regA);
        matvec_acc(W2_s, Scol, DD, regA);
        store_vec(Scol, regA);                 // S = h2 (regA keeps h2)
        // gate = sigmoid(h2 @ Wg + bg); y = gate*h2 + residual
        load_b(bias_s + 4 * DD, regC);
        matvec_acc(Wg_s, Scol, DD, regC);
#pragma unroll
        for (int i = 0; i < 16; i++) {
            float4 g;
            g.x = sigm(regC[i].x); g.y = sigm(regC[i].y);
            g.z = sigm(regC[i].z); g.w = sigm(regC[i].w);
            regC[i].x = fmaf(g.x, regA[i].x, Rcol[(4 * i + 0) * TPB]);
            regC[i].y = fmaf(g.y, regA[i].y, Rcol[(4 * i + 1) * TPB]);
            regC[i].z = fmaf(g.z, regA[i].z, Rcol[(4 * i + 2) * TPB]);
            regC[i].w = fmaf(g.w, regA[i].w, Rcol[(4 * i + 3) * TPB]);
        }
        // LayerNorm over 64 dims (thread-local)
        float mu = 0.f;
#pragma unroll
        for (int i = 0; i < 16; i++)
            mu += regC[i].x + regC[i].y + regC[i].z + regC[i].w;
        mu *= (1.f / 64.f);
        float var = 0.f;
#pragma unroll
        for (int i = 0; i < 16; i++) {
            float dx = regC[i].x - mu, dy = regC[i].y - mu;
            float dz = regC[i].z - mu, dw = regC[i].w - mu;
            var += dx * dx + dy * dy + dz * dz + dw * dw;
        }
        var *= (1.f / 64.f);
        float rs = rsqrtf(var + LN_EPS);
        const float4* g4 = (const float4*)(bias_s + 5 * DD);
        const float4* be4 = (const float4*)(bias_s + 6 * DD);
        float w = wsel[(size_t)token * NVARS + n];
#pragma unroll
        for (int i = 0; i < 16; i++) {
            float4 gm = g4[i], bb = be4[i];
            float yx = fmaf((regC[i].x - mu) * rs, gm.x, bb.x);
            float yy = fmaf((regC[i].y - mu) * rs, gm.y, bb.y);
            float yz = fmaf((regC[i].z - mu) * rs, gm.z, bb.z);
            float yw = fmaf((regC[i].w - mu) * rs, gm.w, bb.w);
            sel[i].x = fmaf(w, yx, sel[i].x);
            sel[i].y = fmaf(w, yy, sel[i].y);
            sel[i].z = fmaf(w, yz, sel[i].z);
            sel[i].w = fmaf(w, yw, sel[i].w);
        }
    }

    float4* outp = (float4*)(selected + (size_t)token * DD);
#pragma unroll
    for (int i = 0; i < 16; i++) outp[i] = sel[i];
}

// ---------------------------------------------------------------------------
extern "C" void kernel_launch(void* const* d_in, const int* in_sizes, int n_in,
                              void* d_out, int out_size) {
    const float* inputs  = (const float*)d_in[0];
    const float* context = (const float*)d_in[1];
    const float* Wt   = (const float*)d_in[2];
    const float* bt   = (const float*)d_in[3];
    const float* Wctx = (const float*)d_in[4];
    const float* W1   = (const float*)d_in[5];
    const float* b1   = (const float*)d_in[6];
    const float* W2   = (const float*)d_in[7];
    const float* b2   = (const float*)d_in[8];
    const float* Wg   = (const float*)d_in[9];
    const float* bg   = (const float*)d_in[10];
    const float* Wp   = (const float*)d_in[11];
    const float* bp   = (const float*)d_in[12];
    const float* gam  = (const float*)d_in[13];
    const float* bet  = (const float*)d_in[14];
    const float* Ws   = (const float*)d_in[15];
    const float* bs   = (const float*)d_in[16];

    float* selected = (float*)d_out;
    float* wout = selected + (size_t)NTOK * DD;  // weights section of output

    cproj_kernel<<<dim3(NB, NVARS), DD>>>(context, Wctx);
    weights_kernel<<<NTOK / TPB, TPB>>>(inputs, Ws, bs, wout);

    size_t smem_bytes = (size_t)(VDIM * DD + 4 * DD * DD + 8 * DD + 2 * DD * TPB) * sizeof(float);
    cudaFuncSetAttribute(vsn_main_kernel,
                         cudaFuncAttributeMaxDynamicSharedMemorySize,
                         (int)smem_bytes);
    vsn_main_kernel<<<NTOK / TPB, TPB, smem_bytes>>>(
        inputs, Wt, bt, W1, b1, W2, b2, Wg, bg, Wp, bp, gam, bet, wout, selected);
}

// round 2
// speedup vs baseline: 1.0517x; 1.0517x over previous
#include <cuda_runtime.h>
#include <math.h>

#define NB 64
#define NT 512
#define NVARS 16
#define VDIM 16
#define DD 64
#define NTOK (NB*NT)
#define TPB 256
#define LN_EPS 1e-3f

typedef unsigned long long u64;

// scratch for context projection [B, N_VARS, D]
__device__ __align__(16) float g_cproj[NB * NVARS * DD];

// ---------------- packed f32x2 helpers ----------------
#define FMA2(d, a, b) asm("fma.rn.f32x2 %0, %1, %2, %0;" : "+l"(d) : "l"(a), "l"(b))
#define ADD2(d, a, b) asm("add.rn.f32x2 %0, %1, %2;" : "=l"(d) : "l"(a), "l"(b))
#define MUL2(d, a, b) asm("mul.rn.f32x2 %0, %1, %2;" : "=l"(d) : "l"(a), "l"(b))

__device__ __forceinline__ void unpack2(u64 v, float& a, float& b) {
    unsigned int x, y;
    asm("mov.b64 {%0,%1}, %2;" : "=r"(x), "=r"(y) : "l"(v));
    a = __uint_as_float(x); b = __uint_as_float(y);
}
__device__ __forceinline__ u64 pack2(float a, float b) {
    u64 v;
    asm("mov.b64 %0, {%1,%2};" : "=l"(v)
        : "r"(__float_as_uint(a)), "r"(__float_as_uint(b)));
    return v;
}
__device__ __forceinline__ u64 dup2(float a) {
    u64 v;
    asm("mov.b64 %0, {%1,%1};" : "=l"(v) : "r"(__float_as_uint(a)));
    return v;
}

// ---------------------------------------------------------------------------
// Kernel A: cproj[b][n][e] = sum_d context[b][d] * Wctx[n][d][e]
// ---------------------------------------------------------------------------
__global__ void cproj_kernel(const float* __restrict__ context,
                             const float* __restrict__ Wctx) {
    int bb = blockIdx.x, n = blockIdx.y, e = threadIdx.x;
    const float* ctx = context + bb * DD;
    const float* W = Wctx + (size_t)n * DD * DD;
    float acc = 0.f;
#pragma unroll 8
    for (int d = 0; d < DD; ++d)
        acc = fmaf(ctx[d], W[d * DD + e], acc);
    g_cproj[((size_t)bb * NVARS + n) * DD + e] = acc;
}

// ---------------------------------------------------------------------------
// Kernel C: selection weights = softmax(inputs @ Ws + bs) -> wout [NTOK][16]
// ---------------------------------------------------------------------------
__global__ __launch_bounds__(TPB) void weights_kernel(
    const float* __restrict__ inputs, const float* __restrict__ Ws,
    const float* __restrict__ bs, float* __restrict__ wout) {
    __shared__ __align__(16) float ws_s[256 * 16];
    __shared__ __align__(16) float bs_s[16];
    int tid = threadIdx.x;
    for (int i = tid; i < 256 * 16; i += TPB) ws_s[i] = Ws[i];
    if (tid < 16) bs_s[tid] = bs[tid];
    __syncthreads();

    int token = blockIdx.x * TPB + tid;
    const float4* xp = (const float4*)(inputs + (size_t)token * 256);
    u64 lg[8];
#pragma unroll
    for (int j = 0; j < 8; j++) lg[j] = ((const u64*)bs_s)[j];

#pragma unroll 4
    for (int f4 = 0; f4 < 64; ++f4) {
        float4 xv = xp[f4];
        const float* wr = ws_s + f4 * 64;
#pragma unroll
        for (int c = 0; c < 4; c++) {
            float x = (c == 0) ? xv.x : (c == 1) ? xv.y : (c == 2) ? xv.z : xv.w;
            u64 x2 = dup2(x);
            const u64* w2 = (const u64*)(wr + c * 16);
#pragma unroll
            for (int j = 0; j < 8; j++) FMA2(lg[j], x2, w2[j]);
        }
    }

    float l[16];
#pragma unroll
    for (int j = 0; j < 8; j++) unpack2(lg[j], l[2 * j], l[2 * j + 1]);
    float mx = l[0];
#pragma unroll
    for (int i = 1; i < 16; i++) mx = fmaxf(mx, l[i]);
    float s = 0.f;
#pragma unroll
    for (int i = 0; i < 16; i++) { l[i] = __expf(l[i] - mx); s += l[i]; }
    float inv = __fdividef(1.f, s);
    float4* op = (float4*)(wout + (size_t)token * 16);
#pragma unroll
    for (int j = 0; j < 4; j++) {
        float4 o;
        o.x = l[4 * j + 0] * inv; o.y = l[4 * j + 1] * inv;
        o.z = l[4 * j + 2] * inv; o.w = l[4 * j + 3] * inv;
        op[j] = o;
    }
}

// ---------------------------------------------------------------------------
// Main fused kernel helpers (packed)
// ---------------------------------------------------------------------------
__device__ __forceinline__ float eluf(float x) {
    return x > 0.f ? x : (__expf(x) - 1.f);
}
__device__ __forceinline__ float sigm(float x) {
    return __fdividef(1.f, 1.f + __expf(-x));
}

// acc(packed pairs) += Scol(packed pairs, stride TPB) @ W (KP*2 rows x 64)
template <int KP>
__device__ __forceinline__ void matvec_acc(const float* __restrict__ W,
                                           const u64* __restrict__ Scol,
                                           u64 acc[32]) {
#pragma unroll 4
    for (int kp = 0; kp < KP; ++kp) {
        u64 apair = Scol[kp * TPB];
        float a0, a1;
        unpack2(apair, a0, a1);
        u64 aa0 = dup2(a0), aa1 = dup2(a1);
        const ulonglong2* w0 = (const ulonglong2*)(W + (2 * kp) * DD);
        const ulonglong2* w1 = (const ulonglong2*)(W + (2 * kp + 1) * DD);
#pragma unroll
        for (int i = 0; i < 16; ++i) {
            ulonglong2 wa = w0[i];
            FMA2(acc[2 * i], aa0, wa.x);
            FMA2(acc[2 * i + 1], aa0, wa.y);
        }
#pragma unroll
        for (int i = 0; i < 16; ++i) {
            ulonglong2 wb = w1[i];
            FMA2(acc[2 * i], aa1, wb.x);
            FMA2(acc[2 * i + 1], aa1, wb.y);
        }
    }
}

__device__ __forceinline__ void store_col(u64* __restrict__ col, const u64 v[32]) {
#pragma unroll
    for (int i = 0; i < 32; i++) col[i * TPB] = v[i];
}

__device__ __forceinline__ void load_b(const float* __restrict__ bsm, u64 v[32]) {
    const u64* b = (const u64*)bsm;
#pragma unroll
    for (int i = 0; i < 32; i++) v[i] = b[i];
}

// ---------------------------------------------------------------------------
// Main fused kernel: per-token chain over 16 vars, weighted selection
// ---------------------------------------------------------------------------
__global__ __launch_bounds__(TPB, 1) void vsn_main_kernel(
    const float* __restrict__ inputs,
    const float* __restrict__ Wt, const float* __restrict__ bt,
    const float* __restrict__ W1, const float* __restrict__ b1,
    const float* __restrict__ W2, const float* __restrict__ b2,
    const float* __restrict__ Wg, const float* __restrict__ bg,
    const float* __restrict__ Wp, const float* __restrict__ bp,
    const float* __restrict__ gamma_, const float* __restrict__ beta_,
    const float* __restrict__ wsel,
    float* __restrict__ selected) {
    extern __shared__ __align__(16) float smem[];
    float* Wt_s = smem;                 // 1024
    float* Wp_s = Wt_s + VDIM * DD;     // 4096 each
    float* W1_s = Wp_s + DD * DD;
    float* W2_s = W1_s + DD * DD;
    float* Wg_s = W2_s + DD * DD;
    float* bias_s = Wg_s + DD * DD;     // 8*64
    u64* S = (u64*)(bias_s + 8 * DD);   // 32*TPB u64
    u64* R = S + 32 * TPB;              // 32*TPB u64

    const int tid = threadIdx.x;
    const int token = blockIdx.x * TPB + tid;
    const int b = token / NT;
    u64* Scol = S + tid;
    u64* Rcol = R + tid;

    u64 sel[32];
#pragma unroll
    for (int i = 0; i < 32; i++) sel[i] = 0ull;

    for (int n = 0; n < NVARS; ++n) {
        __syncthreads();  // previous iter's smem reads done
        // cooperative weight loads (contiguous region)
        {
            const float4* s0 = (const float4*)(Wt + (size_t)n * VDIM * DD);
            float4* d0 = (float4*)Wt_s;
            for (int i = tid; i < 256; i += TPB) d0[i] = s0[i];
            const float4* s1 = (const float4*)(Wp + (size_t)n * DD * DD);
            float4* d1 = (float4*)Wp_s;
            for (int i = tid; i < 1024; i += TPB) d1[i] = s1[i];
            const float4* s2 = (const float4*)(W1 + (size_t)n * DD * DD);
            float4* d2 = (float4*)W1_s;
            for (int i = tid; i < 1024; i += TPB) d2[i] = s2[i];
            const float4* s3 = (const float4*)(W2 + (size_t)n * DD * DD);
            float4* d3 = (float4*)W2_s;
            for (int i = tid; i < 1024; i += TPB) d3[i] = s3[i];
            const float4* s4 = (const float4*)(Wg + (size_t)n * DD * DD);
            float4* d4 = (float4*)Wg_s;
            for (int i = tid; i < 1024; i += TPB) d4[i] = s4[i];
        }
        if (tid < DD) {
            bias_s[0 * DD + tid] = bt[n * DD + tid];
            bias_s[1 * DD + tid] = bp[n * DD + tid];
            bias_s[2 * DD + tid] = b1[n * DD + tid];
            bias_s[3 * DD + tid] = b2[n * DD + tid];
            bias_s[4 * DD + tid] = bg[n * DD + tid];
            bias_s[5 * DD + tid] = gamma_[n * DD + tid];
            bias_s[6 * DD + tid] = beta_[n * DD + tid];
        }
        __syncthreads();

        // stage x slice [16] into S pairs 0..7
        {
            const ulonglong2* xp =
                (const ulonglong2*)(inputs + (size_t)token * 256 + n * VDIM);
#pragma unroll
            for (int i = 0; i < 4; i++) {
                ulonglong2 xv = xp[i];
                Scol[(2 * i + 0) * TPB] = xv.x;
                Scol[(2 * i + 1) * TPB] = xv.y;
            }
        }

        u64 accA[32], accC[32];
        // t = x @ Wt + bt
        load_b(bias_s + 0 * DD, accA);
        matvec_acc<8>(Wt_s, Scol, accA);
        store_col(Scol, accA);                 // S = t
        // residual = t @ Wp + bp
        load_b(bias_s + 1 * DD, accC);
        matvec_acc<32>(Wp_s, Scol, accC);
        store_col(Rcol, accC);                 // R = residual
        // a = t + cproj
        {
            const ulonglong2* cp =
                (const ulonglong2*)(g_cproj + ((size_t)b * NVARS + n) * DD);
#pragma unroll
            for (int i = 0; i < 16; i++) {
                ulonglong2 c2 = cp[i];
                ADD2(accA[2 * i], accA[2 * i], c2.x);
                ADD2(accA[2 * i + 1], accA[2 * i + 1], c2.y);
            }
            store_col(Scol, accA);             // S = a
        }
        // h1 = elu(a @ W1 + b1)
        load_b(bias_s + 2 * DD, accC);
        matvec_acc<32>(W1_s, Scol, accC);
#pragma unroll
        for (int i = 0; i < 32; i++) {
            float e0, e1;
            unpack2(accC[i], e0, e1);
            Scol[i * TPB] = pack2(eluf(e0), eluf(e1));  // S = h1
        }
        // h2 = h1 @ W2 + b2
        load_b(bias_s + 3 * DD, accA);
        matvec_acc<32>(W2_s, Scol, accA);
        store_col(Scol, accA);                 // S = h2 (accA keeps h2)
        // gate = sigmoid(h2 @ Wg + bg); y = gate*h2 + residual
        load_b(bias_s + 4 * DD, accC);
        matvec_acc<32>(Wg_s, Scol, accC);
#pragma unroll
        for (int i = 0; i < 32; i++) {
            float g0, g1;
            unpack2(accC[i], g0, g1);
            u64 g2 = pack2(sigm(g0), sigm(g1));
            u64 y = Rcol[i * TPB];             // y = residual
            FMA2(y, g2, accA[i]);              // y += gate * h2
            accC[i] = y;
        }
        // LayerNorm over 64 dims (packed)
        u64 s2 = accC[0];
#pragma unroll
        for (int i = 1; i < 32; i++) ADD2(s2, s2, accC[i]);
        float s0f, s1f;
        unpack2(s2, s0f, s1f);
        float mu = (s0f + s1f) * (1.f / 64.f);
        u64 negmu = dup2(-mu);
        u64 v2 = 0ull;
#pragma unroll
        for (int i = 0; i < 32; i++) {
            u64 d;
            ADD2(d, accC[i], negmu);
            FMA2(v2, d, d);
        }
        float v0f, v1f;
        unpack2(v2, v0f, v1f);
        float var = (v0f + v1f) * (1.f / 64.f);
        u64 rs2 = dup2(rsqrtf(var + LN_EPS));
        u64 w2 = dup2(wsel[(size_t)token * NVARS + n]);
        const u64* g64 = (const u64*)(bias_s + 5 * DD);
        const u64* be64 = (const u64*)(bias_s + 6 * DD);
#pragma unroll
        for (int i = 0; i < 32; i++) {
            u64 d, t2, y;
            ADD2(d, accC[i], negmu);
            MUL2(t2, d, rs2);
            y = be64[i];
            FMA2(y, t2, g64[i]);               // y = d*rs*gamma + beta
            FMA2(sel[i], w2, y);               // sel += w * y
        }
    }

    ulonglong2* outp = (ulonglong2*)(selected + (size_t)token * DD);
#pragma unroll
    for (int i = 0; i < 16; i++) {
        ulonglong2 o;
        o.x = sel[2 * i]; o.y = sel[2 * i + 1];
        outp[i] = o;
    }
}

// ---------------------------------------------------------------------------
extern "C" void kernel_launch(void* const* d_in, const int* in_sizes, int n_in,
                              void* d_out, int out_size) {
    const float* inputs  = (const float*)d_in[0];
    const float* context = (const float*)d_in[1];
    const float* Wt   = (const float*)d_in[2];
    const float* bt   = (const float*)d_in[3];
    const float* Wctx = (const float*)d_in[4];
    const float* W1   = (const float*)d_in[5];
    const float* b1   = (const float*)d_in[6];
    const float* W2   = (const float*)d_in[7];
    const float* b2   = (const float*)d_in[8];
    const float* Wg   = (const float*)d_in[9];
    const float* bg   = (const float*)d_in[10];
    const float* Wp   = (const float*)d_in[11];
    const float* bp   = (const float*)d_in[12];
    const float* gam  = (const float*)d_in[13];
    const float* bet  = (const float*)d_in[14];
    const float* Ws   = (const float*)d_in[15];
    const float* bs   = (const float*)d_in[16];

    float* selected = (float*)d_out;
    float* wout = selected + (size_t)NTOK * DD;  // weights section of output

    cproj_kernel<<<dim3(NB, NVARS), DD>>>(context, Wctx);
    weights_kernel<<<NTOK / TPB, TPB>>>(inputs, Ws, bs, wout);

    size_t smem_bytes = (size_t)(VDIM * DD + 4 * DD * DD + 8 * DD) * sizeof(float)
                      + (size_t)2 * 32 * TPB * sizeof(u64);
    cudaFuncSetAttribute(vsn_main_kernel,
                         cudaFuncAttributeMaxDynamicSharedMemorySize,
                         (int)smem_bytes);
    vsn_main_kernel<<<NTOK / TPB, TPB, smem_bytes>>>(
        inputs, Wt, bt, W1, b1, W2, b2, Wg, bg, Wp, bp, gam, bet, wout, selected);
}

// round 3
// speedup vs baseline: 1.1420x; 1.0859x over previous
#include <cuda_runtime.h>
#include <math.h>

#define NB 64
#define NT 512
#define NVARS 16
#define VDIM 16
#define DD 64
#define NTOK (NB*NT)
#define TPB 256
#define TOKCTA 128
#define ROWF 72          // padded row: 32 floats | 4 pad | 32 floats | 4 pad
#define HALF_OFF 36      // float offset of half-1 dims within a row
#define LN_EPS 1e-3f

typedef unsigned long long u64;

// scratch for context projection [B, N_VARS, D]
__device__ __align__(16) float g_cproj[NB * NVARS * DD];

// ---------------- packed f32x2 helpers ----------------
#define FMA2(d, a, b) asm("fma.rn.f32x2 %0, %1, %2, %0;" : "+l"(d) : "l"(a), "l"(b))
#define ADD2(d, a, b) asm("add.rn.f32x2 %0, %1, %2;" : "=l"(d) : "l"(a), "l"(b))
#define MUL2(d, a, b) asm("mul.rn.f32x2 %0, %1, %2;" : "=l"(d) : "l"(a), "l"(b))

__device__ __forceinline__ void unpack2(u64 v, float& a, float& b) {
    unsigned int x, y;
    asm("mov.b64 {%0,%1}, %2;" : "=r"(x), "=r"(y) : "l"(v));
    a = __uint_as_float(x); b = __uint_as_float(y);
}
__device__ __forceinline__ u64 pack2(float a, float b) {
    u64 v;
    asm("mov.b64 %0, {%1,%2};" : "=l"(v)
        : "r"(__float_as_uint(a)), "r"(__float_as_uint(b)));
    return v;
}
__device__ __forceinline__ u64 dup2(float a) {
    u64 v;
    asm("mov.b64 %0, {%1,%1};" : "=l"(v) : "r"(__float_as_uint(a)));
    return v;
}

// ---------------------------------------------------------------------------
// Kernel A: cproj[b][n][e] = sum_d context[b][d] * Wctx[n][d][e]
// ---------------------------------------------------------------------------
__global__ void cproj_kernel(const float* __restrict__ context,
                             const float* __restrict__ Wctx) {
    int bb = blockIdx.x, n = blockIdx.y, e = threadIdx.x;
    const float* ctx = context + bb * DD;
    const float* W = Wctx + (size_t)n * DD * DD;
    float acc = 0.f;
#pragma unroll 8
    for (int d = 0; d < DD; ++d)
        acc = fmaf(ctx[d], W[d * DD + e], acc);
    g_cproj[((size_t)bb * NVARS + n) * DD + e] = acc;
}

// ---------------------------------------------------------------------------
// Kernel C: selection weights = softmax(inputs @ Ws + bs) -> wout [NTOK][16]
// ---------------------------------------------------------------------------
__global__ __launch_bounds__(TPB) void weights_kernel(
    const float* __restrict__ inputs, const float* __restrict__ Ws,
    const float* __restrict__ bs, float* __restrict__ wout) {
    __shared__ __align__(16) float ws_s[256 * 16];
    __shared__ __align__(16) float bs_s[16];
    int tid = threadIdx.x;
    for (int i = tid; i < 256 * 16; i += TPB) ws_s[i] = Ws[i];
    if (tid < 16) bs_s[tid] = bs[tid];
    __syncthreads();

    int token = blockIdx.x * TPB + tid;
    const float4* xp = (const float4*)(inputs + (size_t)token * 256);
    u64 lg[8];
#pragma unroll
    for (int j = 0; j < 8; j++) lg[j] = ((const u64*)bs_s)[j];

#pragma unroll 4
    for (int f4 = 0; f4 < 64; ++f4) {
        float4 xv = xp[f4];
        const float* wr = ws_s + f4 * 64;
#pragma unroll
        for (int c = 0; c < 4; c++) {
            float x = (c == 0) ? xv.x : (c == 1) ? xv.y : (c == 2) ? xv.z : xv.w;
            u64 x2 = dup2(x);
            const u64* w2 = (const u64*)(wr + c * 16);
#pragma unroll
            for (int j = 0; j < 8; j++) FMA2(lg[j], x2, w2[j]);
        }
    }

    float l[16];
#pragma unroll
    for (int j = 0; j < 8; j++) unpack2(lg[j], l[2 * j], l[2 * j + 1]);
    float mx = l[0];
#pragma unroll
    for (int i = 1; i < 16; i++) mx = fmaxf(mx, l[i]);
    float s = 0.f;
#pragma unroll
    for (int i = 0; i < 16; i++) { l[i] = __expf(l[i] - mx); s += l[i]; }
    float inv = __fdividef(1.f, s);
    float4* op = (float4*)(wout + (size_t)token * 16);
#pragma unroll
    for (int j = 0; j < 4; j++) {
        float4 o;
        o.x = l[4 * j + 0] * inv; o.y = l[4 * j + 1] * inv;
        o.z = l[4 * j + 2] * inv; o.w = l[4 * j + 3] * inv;
        op[j] = o;
    }
}

// ---------------------------------------------------------------------------
// Main fused kernel helpers
// ---------------------------------------------------------------------------
__device__ __forceinline__ float eluf(float x) {
    return x > 0.f ? x : (__expf(x) - 1.f);
}
__device__ __forceinline__ float sigm(float x) {
    return __fdividef(1.f, 1.f + __expf(-x));
}

// acc[16] (this thread's 32 output dims as f32x2 pairs) +=
//   sum over KP*2 input dims: Scol pairs @ W rows (padded ROWF layout).
// Wbase already includes the half offset.
template <int KP>
__device__ __forceinline__ void matvec(const float* __restrict__ Wbase,
                                       const u64* __restrict__ Scol,
                                       u64 acc[16]) {
#pragma unroll 4
    for (int kp = 0; kp < KP; ++kp) {
        u64 ap = Scol[kp * TOKCTA];
        float a0, a1;
        unpack2(ap, a0, a1);
        u64 aa0 = dup2(a0), aa1 = dup2(a1);
        const ulonglong2* w0 = (const ulonglong2*)(Wbase + (2 * kp) * ROWF);
        const ulonglong2* w1 = (const ulonglong2*)(Wbase + (2 * kp + 1) * ROWF);
#pragma unroll
        for (int i = 0; i < 8; ++i) {
            ulonglong2 wa = w0[i];
            FMA2(acc[2 * i], aa0, wa.x);
            FMA2(acc[2 * i + 1], aa0, wa.y);
        }
#pragma unroll
        for (int i = 0; i < 8; ++i) {
            ulonglong2 wb = w1[i];
            FMA2(acc[2 * i], aa1, wb.x);
            FMA2(acc[2 * i + 1], aa1, wb.y);
        }
    }
}

__device__ __forceinline__ void store_half(u64* __restrict__ col, int half,
                                           const u64 v[16]) {
#pragma unroll
    for (int i = 0; i < 16; i++) col[(half * 16 + i) * TOKCTA] = v[i];
}

__device__ __forceinline__ void load_bias(const float* __restrict__ bsm, int half,
                                          u64 v[16]) {
    const u64* b = (const u64*)(bsm + half * 32);
#pragma unroll
    for (int i = 0; i < 16; i++) v[i] = b[i];
}

// ---------------------------------------------------------------------------
// Main fused kernel: 2 threads per token (lane pair), 32 dims each.
// smem: W (272 rows x 72 floats, padded) | bias (8x64) | wsel (128x16) |
//       S (32x128 u64) | R (32x128 u64)
// ---------------------------------------------------------------------------
__global__ __launch_bounds__(TPB, 1) void vsn_main_kernel(
    const float* __restrict__ inputs,
    const float* __restrict__ Wt, const float* __restrict__ bt,
    const float* __restrict__ W1, const float* __restrict__ b1,
    const float* __restrict__ W2, const float* __restrict__ b2,
    const float* __restrict__ Wg, const float* __restrict__ bg,
    const float* __restrict__ Wp, const float* __restrict__ bp,
    const float* __restrict__ gamma_, const float* __restrict__ beta_,
    const float* __restrict__ wsel,
    float* __restrict__ selected) {
    extern __shared__ __align__(16) float smem[];
    float* W_s = smem;                       // 272 * 72 floats
    float* bias_s = W_s + 272 * ROWF;        // 8 * 64
    float* wsel_s = bias_s + 8 * DD;         // 128 * 16
    u64* S = (u64*)(wsel_s + TOKCTA * NVARS);  // 32*128
    u64* R = S + 32 * TOKCTA;                  // 32*128

    const int tid = threadIdx.x;
    const int pair = tid >> 1;           // token slot within CTA
    const int half = tid & 1;            // which 32 dims
    const int token = blockIdx.x * TOKCTA + pair;
    const int b = (blockIdx.x * TOKCTA) / NT;  // whole CTA in one batch
    u64* Scol = S + pair;
    u64* Rcol = R + pair;

    // stage selection weights for this CTA's tokens (coalesced)
    for (int i = tid; i < TOKCTA * NVARS; i += TPB)
        wsel_s[i] = wsel[(size_t)blockIdx.x * TOKCTA * NVARS + i];

    u64 sel[16];
#pragma unroll
    for (int i = 0; i < 16; i++) sel[i] = 0ull;

    // W_s row blocks: Wt rows [0,16), Wp [16,80), W1 [80,144), W2 [144,208), Wg [208,272)
    for (int n = 0; n < NVARS; ++n) {
        __syncthreads();  // previous iter's weight reads done (also covers wsel_s)
        // cooperative weight staging with padded-row layout
        {
            const float4* s0 = (const float4*)(Wt + (size_t)n * VDIM * DD);
            for (int i = tid; i < 16 * 16; i += TPB) {
                int row = i >> 4, c = i & 15;
                int off = row * ROWF + ((c < 8) ? c * 4 : HALF_OFF + (c - 8) * 4);
                *(float4*)(W_s + off) = s0[i];
            }
            const float* srcs[4] = {Wp + (size_t)n * DD * DD, W1 + (size_t)n * DD * DD,
                                    W2 + (size_t)n * DD * DD, Wg + (size_t)n * DD * DD};
#pragma unroll
            for (int j = 0; j < 4; j++) {
                const float4* sj = (const float4*)srcs[j];
                float* base = W_s + (16 + 64 * j) * ROWF;
                for (int i = tid; i < 64 * 16; i += TPB) {
                    int row = i >> 4, c = i & 15;
                    int off = row * ROWF + ((c < 8) ? c * 4 : HALF_OFF + (c - 8) * 4);
                    *(float4*)(base + off) = sj[i];
                }
            }
        }
        if (tid < DD) {
            bias_s[0 * DD + tid] = bt[n * DD + tid];
            bias_s[1 * DD + tid] = bp[n * DD + tid];
            bias_s[2 * DD + tid] = b1[n * DD + tid];
            bias_s[3 * DD + tid] = b2[n * DD + tid];
            bias_s[4 * DD + tid] = bg[n * DD + tid];
            bias_s[5 * DD + tid] = gamma_[n * DD + tid];
            bias_s[6 * DD + tid] = beta_[n * DD + tid];
            bias_s[7 * DD + tid] = g_cproj[((size_t)b * NVARS + n) * DD + tid];
        }
        __syncthreads();

        // stage x slice [16] into S pairs 0..7 (each half-thread writes 4 pairs)
        {
            const ulonglong2* xp =
                (const ulonglong2*)(inputs + (size_t)token * 256 + n * VDIM + half * 8);
            ulonglong2 x0 = xp[0];
            Scol[(half * 4 + 0) * TOKCTA] = x0.x;
            Scol[(half * 4 + 1) * TOKCTA] = x0.y;
            ulonglong2 x1 = xp[1];
            Scol[(half * 4 + 2) * TOKCTA] = x1.x;
            Scol[(half * 4 + 3) * TOKCTA] = x1.y;
        }
        __syncwarp();

        const float* Wt_b = W_s + half * HALF_OFF;
        const float* Wp_b = W_s + 16 * ROWF + half * HALF_OFF;
        const float* W1_b = W_s + 80 * ROWF + half * HALF_OFF;
        const float* W2_b = W_s + 144 * ROWF + half * HALF_OFF;
        const float* Wg_b = W_s + 208 * ROWF + half * HALF_OFF;

        u64 acc[16];
        // t = x @ Wt + bt
        load_bias(bias_s + 0 * DD, half, acc);
        matvec<8>(Wt_b, Scol, acc);
        __syncwarp();
        store_half(Scol, half, acc);           // S = t
        __syncwarp();
        // residual = t @ Wp + bp
        {
            u64 r[16];
            load_bias(bias_s + 1 * DD, half, r);
            matvec<32>(Wp_b, Scol, r);
            store_half(Rcol, half, r);         // R = residual
        }
        // a = t + cproj  (acc still holds t)
        {
            const u64* cp = (const u64*)(bias_s + 7 * DD + half * 32);
#pragma unroll
            for (int i = 0; i < 16; i++) ADD2(acc[i], acc[i], cp[i]);
            __syncwarp();
            store_half(Scol, half, acc);       // S = a
            __syncwarp();
        }
        // h1 = elu(a @ W1 + b1)
        load_bias(bias_s + 2 * DD, half, acc);
        matvec<32>(W1_b, Scol, acc);
#pragma unroll
        for (int i = 0; i < 16; i++) {
            float e0, e1;
            unpack2(acc[i], e0, e1);
            acc[i] = pack2(eluf(e0), eluf(e1));
        }
        __syncwarp();
        store_half(Scol, half, acc);           // S = h1
        __syncwarp();
        // h2 = h1 @ W2 + b2
        load_bias(bias_s + 3 * DD, half, acc);
        matvec<32>(W2_b, Scol, acc);
        __syncwarp();
        store_half(Scol, half, acc);           // S = h2
        __syncwarp();
        // gate = sigmoid(h2 @ Wg + bg); y = gate*h2 + residual
        load_bias(bias_s + 4 * DD, half, acc);
        matvec<32>(Wg_b, Scol, acc);
#pragma unroll
        for (int i = 0; i < 16; i++) {
            float g0, g1;
            unpack2(acc[i], g0, g1);
            u64 g2 = pack2(sigm(g0), sigm(g1));
            u64 y = Rcol[(half * 16 + i) * TOKCTA];      // residual
            u64 h2 = Scol[(half * 16 + i) * TOKCTA];     // h2
            FMA2(y, g2, h2);
            acc[i] = y;
        }
        // LayerNorm over 64 dims: pair reduction via shfl.xor 1
        u64 s2 = acc[0];
#pragma unroll
        for (int i = 1; i < 16; i++) ADD2(s2, s2, acc[i]);
        float s0f, s1f;
        unpack2(s2, s0f, s1f);
        float part = s0f + s1f;
        float tot = part + __shfl_xor_sync(0xffffffffu, part, 1);
        float mu = tot * (1.f / 64.f);
        u64 negmu = dup2(-mu);
        u64 v2 = 0ull;
#pragma unroll
        for (int i = 0; i < 16; i++) {
            u64 d;
            ADD2(d, acc[i], negmu);
            FMA2(v2, d, d);
        }
        float v0f, v1f;
        unpack2(v2, v0f, v1f);
        float vpart = v0f + v1f;
        float vtot = vpart + __shfl_xor_sync(0xffffffffu, vpart, 1);
        float var = vtot * (1.f / 64.f);
        u64 rs2 = dup2(rsqrtf(var + LN_EPS));
        u64 w2 = dup2(wsel_s[pair * NVARS + n]);
        const u64* g64 = (const u64*)(bias_s + 5 * DD + half * 32);
        const u64* be64 = (const u64*)(bias_s + 6 * DD + half * 32);
#pragma unroll
        for (int i = 0; i < 16; i++) {
            u64 d, t2, y;
            ADD2(d, acc[i], negmu);
            MUL2(t2, d, rs2);
            y = be64[i];
            FMA2(y, t2, g64[i]);               // y = d*rs*gamma + beta
            FMA2(sel[i], w2, y);               // sel += w * y
        }
    }

    ulonglong2* outp = (ulonglong2*)(selected + (size_t)token * DD + half * 32);
#pragma unroll
    for (int i = 0; i < 8; i++) {
        ulonglong2 o;
        o.x = sel[2 * i]; o.y = sel[2 * i + 1];
        outp[i] = o;
    }
}

// ---------------------------------------------------------------------------
extern "C" void kernel_launch(void* const* d_in, const int* in_sizes, int n_in,
                              void* d_out, int out_size) {
    const float* inputs  = (const float*)d_in[0];
    const float* context = (const float*)d_in[1];
    const float* Wt   = (const float*)d_in[2];
    const float* bt   = (const float*)d_in[3];
    const float* Wctx = (const float*)d_in[4];
    const float* W1   = (const float*)d_in[5];
    const float* b1   = (const float*)d_in[6];
    const float* W2   = (const float*)d_in[7];
    const float* b2   = (const float*)d_in[8];
    const float* Wg   = (const float*)d_in[9];
    const float* bg   = (const float*)d_in[10];
    const float* Wp   = (const float*)d_in[11];
    const float* bp   = (const float*)d_in[12];
    const float* gam  = (const float*)d_in[13];
    const float* bet  = (const float*)d_in[14];
    const float* Ws   = (const float*)d_in[15];
    const float* bs   = (const float*)d_in[16];

    float* selected = (float*)d_out;
    float* wout = selected + (size_t)NTOK * DD;  // weights section of output

    cproj_kernel<<<dim3(NB, NVARS), DD>>>(context, Wctx);
    weights_kernel<<<NTOK / TPB, TPB>>>(inputs, Ws, bs, wout);

    size_t smem_bytes = (size_t)(272 * ROWF + 8 * DD + TOKCTA * NVARS) * sizeof(float)
                      + (size_t)2 * 32 * TOKCTA * sizeof(u64);
    cudaFuncSetAttribute(vsn_main_kernel,
                         cudaFuncAttributeMaxDynamicSharedMemorySize,
                         (int)smem_bytes);
    vsn_main_kernel<<<NTOK / TOKCTA, TPB, smem_bytes>>>(
        inputs, Wt, bt, W1, b1, W2, b2, Wg, bg, Wp, bp, gam, bet, wout, selected);
}

// round 4
// speedup vs baseline: 1.5821x; 1.3853x over previous
#include <cuda_runtime.h>
#include <math.h>

#define NB 64
#define NT 512
#define NVARS 16
#define VDIM 16
#define DD 64
#define NTOK (NB*NT)
#define TPB 256
#define TOKCTA 256
#define SS 256           // token-slot stride in S/R
#define ROWF 72          // padded row: 32 floats | 4 pad | 32 floats | 4 pad
#define HALF_OFF 36
#define LN_EPS 1e-3f

typedef unsigned long long u64;

// ---------------- packed f32x2 helpers ----------------
#define FMA2(d, a, b) asm("fma.rn.f32x2 %0, %1, %2, %0;" : "+l"(d) : "l"(a), "l"(b))
#define ADD2(d, a, b) asm("add.rn.f32x2 %0, %1, %2;" : "=l"(d) : "l"(a), "l"(b))
#define MUL2(d, a, b) asm("mul.rn.f32x2 %0, %1, %2;" : "=l"(d) : "l"(a), "l"(b))

__device__ __forceinline__ void unpack2(u64 v, float& a, float& b) {
    unsigned int x, y;
    asm("mov.b64 {%0,%1}, %2;" : "=r"(x), "=r"(y) : "l"(v));
    a = __uint_as_float(x); b = __uint_as_float(y);
}
__device__ __forceinline__ u64 pack2(float a, float b) {
    u64 v;
    asm("mov.b64 %0, {%1,%2};" : "=l"(v)
        : "r"(__float_as_uint(a)), "r"(__float_as_uint(b)));
    return v;
}
__device__ __forceinline__ u64 dup2(float a) {
    u64 v;
    asm("mov.b64 %0, {%1,%1};" : "=l"(v) : "r"(__float_as_uint(a)));
    return v;
}

__device__ __forceinline__ float eluf(float x) {
    return x > 0.f ? x : (__expf(x) - 1.f);
}
__device__ __forceinline__ float sigm(float x) {
    return __fdividef(1.f, 1.f + __expf(-x));
}

// smem float offsets (16B-aligned blocks)
#define OFF_S      0                       // u64[32*256] = 65536 B
#define OFF_R      (65536/4)               // u64[32*256]
#define OFF_W      (131072/4)              // 272*72 floats = 78336 B
#define OFF_BIAS   (OFF_W + 272*ROWF)      // 7*64 floats
#define OFF_CPROJ  (OFF_BIAS + 7*DD)       // 16*64 floats
#define OFF_WSEL   (OFF_CPROJ + NVARS*DD)  // 256*16 floats
#define OFF_CTX    (OFF_WSEL + TOKCTA*NVARS) // 64 floats
#define SMEM_FLOATS (OFF_CTX + DD)

// both tokens' 32-dim halves accumulated against shared weight loads
template <int KP>
__device__ __forceinline__ void matvec2(const float* __restrict__ Wbase,
                                        const u64* __restrict__ Sc0,
                                        const u64* __restrict__ Sc1,
                                        u64 a0[16], u64 a1[16]) {
#pragma unroll 2
    for (int kp = 0; kp < KP; ++kp) {
        u64 p0 = Sc0[kp * SS], p1 = Sc1[kp * SS];
        float x00, x01, x10, x11;
        unpack2(p0, x00, x01);
        unpack2(p1, x10, x11);
        u64 a00 = dup2(x00), a01 = dup2(x01);
        u64 a10 = dup2(x10), a11 = dup2(x11);
        const ulonglong2* w0 = (const ulonglong2*)(Wbase + (2 * kp) * ROWF);
        const ulonglong2* w1 = (const ulonglong2*)(Wbase + (2 * kp + 1) * ROWF);
#pragma unroll
        for (int i = 0; i < 8; ++i) {
            ulonglong2 w = w0[i];
            FMA2(a0[2 * i],     a00, w.x);
            FMA2(a0[2 * i + 1], a00, w.y);
            FMA2(a1[2 * i],     a10, w.x);
            FMA2(a1[2 * i + 1], a10, w.y);
        }
#pragma unroll
        for (int i = 0; i < 8; ++i) {
            ulonglong2 w = w1[i];
            FMA2(a0[2 * i],     a01, w.x);
            FMA2(a0[2 * i + 1], a01, w.y);
            FMA2(a1[2 * i],     a11, w.x);
            FMA2(a1[2 * i + 1], a11, w.y);
        }
    }
}

__device__ __forceinline__ void store_half(u64* __restrict__ col, int hf,
                                           const u64 v[16]) {
#pragma unroll
    for (int i = 0; i < 16; i++) col[(hf * 16 + i) * SS] = v[i];
}

__device__ __forceinline__ void load_bias(const float* __restrict__ bsm, int hf,
                                          u64 v[16]) {
    const u64* b = (const u64*)(bsm + hf * 32);
#pragma unroll
    for (int i = 0; i < 16; i++) v[i] = b[i];
}

// ---------------------------------------------------------------------------
__global__ __launch_bounds__(TPB, 1) void vsn_fused_kernel(
    const float* __restrict__ inputs, const float* __restrict__ context,
    const float* __restrict__ Wt, const float* __restrict__ bt,
    const float* __restrict__ Wctx,
    const float* __restrict__ W1, const float* __restrict__ b1,
    const float* __restrict__ W2, const float* __restrict__ b2,
    const float* __restrict__ Wg, const float* __restrict__ bg,
    const float* __restrict__ Wp, const float* __restrict__ bp,
    const float* __restrict__ gamma_, const float* __restrict__ beta_,
    const float* __restrict__ Ws, const float* __restrict__ bs,
    float* __restrict__ selected, float* __restrict__ wout) {
    extern __shared__ __align__(16) float smem[];
    u64* S = (u64*)(smem + OFF_S);
    u64* R = (u64*)(smem + OFF_R);
    float* W_s = smem + OFF_W;
    float* bias_s = smem + OFF_BIAS;
    float* cproj_s = smem + OFF_CPROJ;
    float* wsel_s = smem + OFF_WSEL;
    float* ctx_s = smem + OFF_CTX;

    const int tid = threadIdx.x;
    const int pair = tid >> 1;
    const int hf = tid & 1;
    const int base = blockIdx.x * TOKCTA;
    const int tok0 = base + pair;
    const int tok1 = base + 128 + pair;
    const int b = base / NT;  // all 256 tokens share one batch row
    u64* Sc0 = S + pair;
    u64* Sc1 = S + 128 + pair;
    u64* Rc0 = R + pair;
    u64* Rc1 = R + 128 + pair;

    // ---------- phase 0: stage Ws/bs/ctx ----------
    {
        const float4* s = (const float4*)Ws;
        float4* d = (float4*)W_s;
        for (int i = tid; i < 1024; i += TPB) d[i] = s[i];
        if (tid < 16) bias_s[tid] = bs[tid];
        if (tid < DD) ctx_s[tid] = context[(size_t)b * DD + tid];
    }
    __syncthreads();

    // ---------- phase 1a: per-token softmax (1 token/thread) ----------
    {
        int token = base + tid;
        const float4* xp = (const float4*)(inputs + (size_t)token * 256);
        u64 lg[8];
#pragma unroll
        for (int j = 0; j < 8; j++) lg[j] = ((const u64*)bias_s)[j];
#pragma unroll 4
        for (int f4 = 0; f4 < 64; ++f4) {
            float4 xv = xp[f4];
            const float* wr = W_s + f4 * 64;
#pragma unroll
            for (int c = 0; c < 4; c++) {
                float x = (c == 0) ? xv.x : (c == 1) ? xv.y : (c == 2) ? xv.z : xv.w;
                u64 x2 = dup2(x);
                const u64* w2 = (const u64*)(wr + c * 16);
#pragma unroll
                for (int j = 0; j < 8; j++) FMA2(lg[j], x2, w2[j]);
            }
        }
        float l[16];
#pragma unroll
        for (int j = 0; j < 8; j++) unpack2(lg[j], l[2 * j], l[2 * j + 1]);
        float mx = l[0];
#pragma unroll
        for (int i = 1; i < 16; i++) mx = fmaxf(mx, l[i]);
        float sum = 0.f;
#pragma unroll
        for (int i = 0; i < 16; i++) { l[i] = __expf(l[i] - mx); sum += l[i]; }
        float inv = __fdividef(1.f, sum);
        float4* gp = (float4*)(wout + (size_t)token * 16);
        float4* sp = (float4*)(wsel_s + tid * 16);
#pragma unroll
        for (int j = 0; j < 4; j++) {
            float4 o;
            o.x = l[4 * j + 0] * inv; o.y = l[4 * j + 1] * inv;
            o.z = l[4 * j + 2] * inv; o.w = l[4 * j + 3] * inv;
            gp[j] = o;
            sp[j] = o;
        }
    }

    // ---------- phase 1b: cproj for this CTA's batch row ----------
    {
        int n = tid >> 4;            // 0..15
        int e = (tid & 15) * 4;      // 0..60
        const float* W = Wctx + (size_t)n * DD * DD;
        float4 acc = make_float4(0.f, 0.f, 0.f, 0.f);
#pragma unroll 8
        for (int d = 0; d < DD; ++d) {
            float c = ctx_s[d];
            float4 w = *(const float4*)(W + d * DD + e);
            acc.x = fmaf(c, w.x, acc.x); acc.y = fmaf(c, w.y, acc.y);
            acc.z = fmaf(c, w.z, acc.z); acc.w = fmaf(c, w.w, acc.w);
        }
        *(float4*)(cproj_s + n * DD + e) = acc;
    }

    u64 sel0[16], sel1[16];
#pragma unroll
    for (int i = 0; i < 16; i++) { sel0[i] = 0ull; sel1[i] = 0ull; }

    // W_s blocks: Wt [0,16) rows, Wp [16,80), W1 [80,144), W2 [144,208), Wg [208,272)
    for (int n = 0; n < NVARS; ++n) {
        __syncthreads();
        // weight staging, padded-row layout
        {
            const float4* s0 = (const float4*)(Wt + (size_t)n * VDIM * DD);
            for (int i = tid; i < 16 * 16; i += TPB) {
                int row = i >> 4, c = i & 15;
                int off = row * ROWF + ((c < 8) ? c * 4 : HALF_OFF + (c - 8) * 4);
                *(float4*)(W_s + off) = s0[i];
            }
            const float* srcs[4] = {Wp + (size_t)n * DD * DD, W1 + (size_t)n * DD * DD,
                                    W2 + (size_t)n * DD * DD, Wg + (size_t)n * DD * DD};
#pragma unroll
            for (int j = 0; j < 4; j++) {
                const float4* sj = (const float4*)srcs[j];
                float* dst = W_s + (16 + 64 * j) * ROWF;
                for (int i = tid; i < 64 * 16; i += TPB) {
                    int row = i >> 4, c = i & 15;
                    int off = row * ROWF + ((c < 8) ? c * 4 : HALF_OFF + (c - 8) * 4);
                    *(float4*)(dst + off) = sj[i];
                }
            }
        }
        if (tid < DD) {
            bias_s[0 * DD + tid] = bt[n * DD + tid];
            bias_s[1 * DD + tid] = bp[n * DD + tid];
            bias_s[2 * DD + tid] = b1[n * DD + tid];
            bias_s[3 * DD + tid] = b2[n * DD + tid];
            bias_s[4 * DD + tid] = bg[n * DD + tid];
            bias_s[5 * DD + tid] = gamma_[n * DD + tid];
            bias_s[6 * DD + tid] = beta_[n * DD + tid];
        }
        __syncthreads();

        // stage x slices (rows 0..7), both tokens
        {
            const ulonglong2* x0 =
                (const ulonglong2*)(inputs + (size_t)tok0 * 256 + n * VDIM + hf * 8);
            ulonglong2 v = x0[0];
            Sc0[(hf * 4 + 0) * SS] = v.x; Sc0[(hf * 4 + 1) * SS] = v.y;
            v = x0[1];
            Sc0[(hf * 4 + 2) * SS] = v.x; Sc0[(hf * 4 + 3) * SS] = v.y;
            const ulonglong2* x1 =
                (const ulonglong2*)(inputs + (size_t)tok1 * 256 + n * VDIM + hf * 8);
            v = x1[0];
            Sc1[(hf * 4 + 0) * SS] = v.x; Sc1[(hf * 4 + 1) * SS] = v.y;
            v = x1[1];
            Sc1[(hf * 4 + 2) * SS] = v.x; Sc1[(hf * 4 + 3) * SS] = v.y;
        }
        __syncwarp();

        const float* Wt_b = W_s + hf * HALF_OFF;
        const float* Wp_b = W_s + 16 * ROWF + hf * HALF_OFF;
        const float* W1_b = W_s + 80 * ROWF + hf * HALF_OFF;
        const float* W2_b = W_s + 144 * ROWF + hf * HALF_OFF;
        const float* Wg_b = W_s + 208 * ROWF + hf * HALF_OFF;

        u64 acc0[16], acc1[16];
        // t = x @ Wt + bt
        load_bias(bias_s + 0 * DD, hf, acc0);
        load_bias(bias_s + 0 * DD, hf, acc1);
        matvec2<8>(Wt_b, Sc0, Sc1, acc0, acc1);
        __syncwarp();
        store_half(Sc0, hf, acc0); store_half(Sc1, hf, acc1);   // S = t
        __syncwarp();
        // residual = t @ Wp + bp -> R
        load_bias(bias_s + 1 * DD, hf, acc0);
        load_bias(bias_s + 1 * DD, hf, acc1);
        matvec2<32>(Wp_b, Sc0, Sc1, acc0, acc1);
        store_half(Rc0, hf, acc0); store_half(Rc1, hf, acc1);
        __syncwarp();
        // a = t + cproj (update S in place: this thread's 16 rows)
        {
            const u64* cp = (const u64*)(cproj_s + n * DD + hf * 32);
#pragma unroll
            for (int i = 0; i < 16; i++) {
                u64 c = cp[i];
                u64 v0 = Sc0[(hf * 16 + i) * SS];
                u64 v1 = Sc1[(hf * 16 + i) * SS];
                ADD2(v0, v0, c); ADD2(v1, v1, c);
                Sc0[(hf * 16 + i) * SS] = v0;
                Sc1[(hf * 16 + i) * SS] = v1;
            }
        }
        __syncwarp();
        // h1 = elu(a @ W1 + b1)
        load_bias(bias_s + 2 * DD, hf, acc0);
        load_bias(bias_s + 2 * DD, hf, acc1);
        matvec2<32>(W1_b, Sc0, Sc1, acc0, acc1);
#pragma unroll
        for (int i = 0; i < 16; i++) {
            float e0, e1;
            unpack2(acc0[i], e0, e1); acc0[i] = pack2(eluf(e0), eluf(e1));
            unpack2(acc1[i], e0, e1); acc1[i] = pack2(eluf(e0), eluf(e1));
        }
        __syncwarp();
        store_half(Sc0, hf, acc0); store_half(Sc1, hf, acc1);   // S = h1
        __syncwarp();
        // h2 = h1 @ W2 + b2
        load_bias(bias_s + 3 * DD, hf, acc0);
        load_bias(bias_s + 3 * DD, hf, acc1);
        matvec2<32>(W2_b, Sc0, Sc1, acc0, acc1);
        __syncwarp();
        store_half(Sc0, hf, acc0); store_half(Sc1, hf, acc1);   // S = h2
        __syncwarp();
        // gate logits
        load_bias(bias_s + 4 * DD, hf, acc0);
        load_bias(bias_s + 4 * DD, hf, acc1);
        matvec2<32>(Wg_b, Sc0, Sc1, acc0, acc1);
#pragma unroll
        for (int i = 0; i < 16; i++) {
            float g0, g1;
            unpack2(acc0[i], g0, g1);
            u64 gpk = pack2(sigm(g0), sigm(g1));
            u64 y = Rc0[(hf * 16 + i) * SS];
            u64 h2 = Sc0[(hf * 16 + i) * SS];
            FMA2(y, gpk, h2);
            acc0[i] = y;
            unpack2(acc1[i], g0, g1);
            gpk = pack2(sigm(g0), sigm(g1));
            y = Rc1[(hf * 16 + i) * SS];
            h2 = Sc1[(hf * 16 + i) * SS];
            FMA2(y, gpk, h2);
            acc1[i] = y;
        }
        // LayerNorm + weighted select, token 0
        {
            u64 s2 = acc0[0];
#pragma unroll
            for (int i = 1; i < 16; i++) ADD2(s2, s2, acc0[i]);
            float sa, sb; unpack2(s2, sa, sb);
            float part = sa + sb;
            float mu = (part + __shfl_xor_sync(0xffffffffu, part, 1)) * (1.f / 64.f);
            u64 negmu = dup2(-mu);
            u64 v2 = 0ull;
#pragma unroll
            for (int i = 0; i < 16; i++) {
                u64 d; ADD2(d, acc0[i], negmu); FMA2(v2, d, d);
            }
            float va, vb; unpack2(v2, va, vb);
            float vpart = va + vb;
            float var = (vpart + __shfl_xor_sync(0xffffffffu, vpart, 1)) * (1.f / 64.f);
            u64 rs2 = dup2(rsqrtf(var + LN_EPS));
            u64 w2 = dup2(wsel_s[pair * NVARS + n]);
            const u64* g64 = (const u64*)(bias_s + 5 * DD + hf * 32);
            const u64* be64 = (const u64*)(bias_s + 6 * DD + hf * 32);
#pragma unroll
            for (int i = 0; i < 16; i++) {
                u64 d, t2, y;
                ADD2(d, acc0[i], negmu);
                MUL2(t2, d, rs2);
                y = be64[i];
                FMA2(y, t2, g64[i]);
                FMA2(sel0[i], w2, y);
            }
        }
        // token 1
        {
            u64 s2 = acc1[0];
#pragma unroll
            for (int i = 1; i < 16; i++) ADD2(s2, s2, acc1[i]);
            float sa, sb; unpack2(s2, sa, sb);
            float part = sa + sb;
            float mu = (part + __shfl_xor_sync(0xffffffffu, part, 1)) * (1.f / 64.f);
            u64 negmu = dup2(-mu);
            u64 v2 = 0ull;
#pragma unroll
            for (int i = 0; i < 16; i++) {
                u64 d; ADD2(d, acc1[i], negmu); FMA2(v2, d, d);
            }
            float va, vb; unpack2(v2, va, vb);
            float vpart = va + vb;
            float var = (vpart + __shfl_xor_sync(0xffffffffu, vpart, 1)) * (1.f / 64.f);
            u64 rs2 = dup2(rsqrtf(var + LN_EPS));
            u64 w2 = dup2(wsel_s[(128 + pair) * NVARS + n]);
            const u64* g64 = (const u64*)(bias_s + 5 * DD + hf * 32);
            const u64* be64 = (const u64*)(bias_s + 6 * DD + hf * 32);
#pragma unroll
            for (int i = 0; i < 16; i++) {
                u64 d, t2, y;
                ADD2(d, acc1[i], negmu);
                MUL2(t2, d, rs2);
                y = be64[i];
                FMA2(y, t2, g64[i]);
                FMA2(sel1[i], w2, y);
            }
        }
    }

    ulonglong2* o0 = (ulonglong2*)(selected + (size_t)tok0 * DD + hf * 32);
    ulonglong2* o1 = (ulonglong2*)(selected + (size_t)tok1 * DD + hf * 32);
#pragma unroll
    for (int i = 0; i < 8; i++) {
        ulonglong2 v;
        v.x = sel0[2 * i]; v.y = sel0[2 * i + 1];
        o0[i] = v;
        v.x = sel1[2 * i]; v.y = sel1[2 * i + 1];
        o1[i] = v;
    }
}

// ---------------------------------------------------------------------------
extern "C" void kernel_launch(void* const* d_in, const int* in_sizes, int n_in,
                              void* d_out, int out_size) {
    const float* inputs  = (const float*)d_in[0];
    const float* context = (const float*)d_in[1];
    const float* Wt   = (const float*)d_in[2];
    const float* bt   = (const float*)d_in[3];
    const float* Wctx = (const float*)d_in[4];
    const float* W1   = (const float*)d_in[5];
    const float* b1   = (const float*)d_in[6];
    const float* W2   = (const float*)d_in[7];
    const float* b2   = (const float*)d_in[8];
    const float* Wg   = (const float*)d_in[9];
    const float* bg   = (const float*)d_in[10];
    const float* Wp   = (const float*)d_in[11];
    const float* bp   = (const float*)d_in[12];
    const float* gam  = (const float*)d_in[13];
    const float* bet  = (const float*)d_in[14];
    const float* Ws   = (const float*)d_in[15];
    const float* bs   = (const float*)d_in[16];

    float* selected = (float*)d_out;
    float* wout = selected + (size_t)NTOK * DD;

    size_t smem_bytes = (size_t)SMEM_FLOATS * sizeof(float);
    cudaFuncSetAttribute(vsn_fused_kernel,
                         cudaFuncAttributeMaxDynamicSharedMemorySize,
                         (int)smem_bytes);
    vsn_fused_kernel<<<NTOK / TOKCTA, TPB, smem_bytes>>>(
        inputs, context, Wt, bt, Wctx, W1, b1, W2, b2, Wg, bg, Wp, bp,
        gam, bet, Ws, bs, selected, wout);
}